// round 4
// baseline (speedup 1.0000x reference)
#include <cuda_runtime.h>

// SNN recurrence: B=1024, T=1024, H=32, I=2.
// One warp per 2 batches; lane = hidden unit; each thread runs TWO batches'
// chains packed in f32x2, with ALL mul/add expressed as FFMA2 via bit-exact
// identities:   mul(a,b) == fma(a,b,-0)   add(a,b) == fma(1,a,b)
// Spikes carried negated (-1 / -0) so subtraction is a packed add, and the
// soma input bs*s is one FFMA2: sneg*(-bs) + (-0).
// This reproduces the scalar reference-order trajectory bit-exactly
// (rel_err was 0.0 for the scalar version).

#define TT 1024

typedef unsigned long long u64;
union P2 { float2 f; u64 u; };

#define NEG0 0x8000000080000000ULL   // (-0.0f, -0.0f)
#define ONE2 0x3f8000003f800000ULL   // ( 1.0f,  1.0f)

__device__ __forceinline__ u64 ffma2(u64 a, u64 b, u64 c) {
    u64 r;
    asm("fma.rn.f32x2 %0, %1, %2, %3;" : "=l"(r) : "l"(a), "l"(b), "l"(c));
    return r;
}
__device__ __forceinline__ u64 pack2(float lo, float hi) {
    P2 p; p.f.x = lo; p.f.y = hi; return p.u;
}

struct St { u64 v, V, sneg, Sneg, accn; };

template <bool ACC>
__device__ __forceinline__ void run32(St& st, const ulonglong2* __restrict__ buf,
                                      u64 W0, u64 W1, u64 BG, u64 AG, u64 AS, u64 NBS)
{
    #pragma unroll
    for (int i = 0; i < 32; ++i) {
        ulonglong2 q = buf[i];            // q.x = (b0.x0, b1.x0), q.y = (b0.x1, b1.x1)

        // gi = x0*w0 + x1*w1 ; u = (1-ag)*gi   (reference order, single-rounded ops)
        u64 t0 = ffma2(q.x, W0, NEG0);            // mul
        u64 t1 = ffma2(q.y, W1, NEG0);            // mul
        u64 gi = ffma2(ONE2, t0, t1);             // add
        u64 u  = ffma2(BG, gi, NEG0);             // mul

        // v = (ag*v + u) + sneg
        u64 a = ffma2(AG, st.v, NEG0);            // mul
        a     = ffma2(ONE2, a, u);                // add
        st.v  = ffma2(ONE2, a, st.sneg);          // add (subtract spike)

        P2 pv; pv.u = st.v;
        P2 ps;
        ps.f.x = (pv.f.x > 1.0f) ? -1.0f : -0.0f;
        ps.f.y = (pv.f.y > 1.0f) ? -1.0f : -0.0f;
        st.sneg = ps.u;

        // m = bs * s  ==  sneg * (-bs) + (-0)
        u64 m = ffma2(st.sneg, NBS, NEG0);

        // V = (as*V + m) + Sneg
        u64 b = ffma2(AS, st.V, NEG0);            // mul
        b     = ffma2(ONE2, b, m);                // add
        st.V  = ffma2(ONE2, b, st.Sneg);          // add

        P2 pV; pV.u = st.V;
        P2 pS;
        pS.f.x = (pV.f.x > 1.0f) ? -1.0f : -0.0f;
        pS.f.y = (pV.f.y > 1.0f) ? -1.0f : -0.0f;
        st.Sneg = pS.u;

        if (ACC) st.accn = ffma2(ONE2, st.accn, st.Sneg);
    }
}

__global__ __launch_bounds__(128, 8)
void snn_kernel(const float* __restrict__ x,
                const float* __restrict__ Wg,     // [32,2]
                const float* __restrict__ tau_g,  // [32]
                const float* __restrict__ tau_s,  // [32]
                const float* __restrict__ Wout,   // [32]
                const float* __restrict__ bout,   // [1]
                float* __restrict__ out)          // [1024]
{
    const int lane = threadIdx.x & 31;
    const int wib  = threadIdx.x >> 5;
    const int gw   = blockIdx.x * 4 + wib;   // 0..511
    const int b0   = gw * 2;

    __shared__ ulonglong2 sbuf[4][2][32];    // [warp][double buffer][step]

    const float w0 = Wg[2 * lane];
    const float w1 = Wg[2 * lane + 1];
    const float ag = 1.0f / (1.0f + expf(-tau_g[lane]));
    const float bg = 1.0f - ag;
    const float as = 1.0f / (1.0f + expf(-tau_s[lane]));
    const float bs = 1.0f - as;

    const u64 W0  = pack2(w0, w0);
    const u64 W1  = pack2(w1, w1);
    const u64 AG  = pack2(ag, ag);
    const u64 BG  = pack2(bg, bg);
    const u64 AS  = pack2(as, as);
    const u64 NBS = pack2(-bs, -bs);

    const float2* xp0 = reinterpret_cast<const float2*>(x) + (size_t)b0 * TT;
    const float2* xp1 = xp0 + TT;

    St st;
    st.v = st.V = 0ULL;          // (+0, +0)
    st.sneg = st.Sneg = NEG0;    // (-0, -0) == negated zero spike
    st.accn = 0ULL;

    // Prime buffer 0
    float2 g0 = xp0[lane], g1 = xp1[lane];
    sbuf[wib][0][lane] = make_ulonglong2(pack2(g0.x, g1.x), pack2(g0.y, g1.y));
    __syncwarp();
    int cur = 0;

    #pragma unroll 1
    for (int chunk = 0; chunk < 24; ++chunk) {
        g0 = xp0[(chunk + 1) * 32 + lane];
        g1 = xp1[(chunk + 1) * 32 + lane];
        run32<false>(st, sbuf[wib][cur], W0, W1, BG, AG, AS, NBS);
        sbuf[wib][cur ^ 1][lane] = make_ulonglong2(pack2(g0.x, g1.x), pack2(g0.y, g1.y));
        __syncwarp();
        cur ^= 1;
    }
    #pragma unroll 1
    for (int chunk = 24; chunk < 32; ++chunk) {
        if (chunk + 1 < 32) {
            g0 = xp0[(chunk + 1) * 32 + lane];
            g1 = xp1[(chunk + 1) * 32 + lane];
        }
        run32<true>(st, sbuf[wib][cur], W0, W1, BG, AG, AS, NBS);
        if (chunk + 1 < 32) {
            sbuf[wib][cur ^ 1][lane] = make_ulonglong2(pack2(g0.x, g1.x), pack2(g0.y, g1.y));
        }
        __syncwarp();
        cur ^= 1;
    }

    // out[b] = sum_h cnt_h * Wout[h] + bout   (same reduction tree as before)
    P2 pa; pa.u = st.accn;
    const float wl = Wout[lane];
    float vx = -pa.f.x * wl;
    float vy = -pa.f.y * wl;
    #pragma unroll
    for (int off = 16; off; off >>= 1) {
        vx += __shfl_xor_sync(0xffffffffu, vx, off);
        vy += __shfl_xor_sync(0xffffffffu, vy, off);
    }
    if (lane == 0) {
        const float bb = bout[0];
        out[b0]     = vx + bb;
        out[b0 + 1] = vy + bb;
    }
}

extern "C" void kernel_launch(void* const* d_in, const int* in_sizes, int n_in,
                              void* d_out, int out_size) {
    const float* x    = (const float*)d_in[0];
    const float* Wg   = (const float*)d_in[1];
    const float* taug = (const float*)d_in[2];
    const float* taus = (const float*)d_in[3];
    const float* Wout = (const float*)d_in[4];
    const float* bout = (const float*)d_in[5];
    float* out = (float*)d_out;

    // 512 warps (2 batches each): 128 blocks x 128 threads
    snn_kernel<<<128, 128>>>(x, Wg, taug, taus, Wout, bout, out);
}